// round 6
// baseline (speedup 1.0000x reference)
#include <cuda_runtime.h>
#include <cuda_fp16.h>
#include <cstdint>

// ---------------------------------------------------------------------------
// Gazs cell, legacy tensor-core path.
// R6: fp16-accumulate HMMA (candidate 2x issue rate vs f32-acc) with
// two-level accumulation: f16 acc for 128 k-elements, spilled to fp32 regs.
// Geometry: 512 thr, CTA 128 x 192 B-rows (64 gate cols), warp m32 x n48.
// ---------------------------------------------------------------------------

#define BM 128
#define BN_GATE 64
#define BN 192                     // 3 gates * 64 cols (B rows)
#define KC 32                      // fp16 k per stage (64B rows)
#define NSTAGES 4
#define ROW_BYTES 80               // 64B data + 16B pad
#define A_TILE (BM * ROW_BYTES)            // 10240
#define B_TILE (BN * ROW_BYTES)            // 15360
#define STAGE  (A_TILE + B_TILE)           // 25600
#define DYN_SMEM (NSTAGES * STAGE)         // 102400

#define BATCH 8192
#define HDIM  1024
#define KDIM  4096

__device__ __align__(16) __half A16[(size_t)BATCH * KDIM];
__device__ __align__(16) __half W16[(size_t)3 * HDIM * KDIM];

// ---- helpers ---------------------------------------------------------------
__device__ __forceinline__ uint32_t smem_u32(const void* p) {
    uint32_t a;
    asm("{ .reg .u64 t; cvta.to.shared.u64 t, %1; cvt.u32.u64 %0, t; }" : "=r"(a) : "l"(p));
    return a;
}
__device__ __forceinline__ void cp16(uint32_t dst, const void* src) {
    asm volatile("cp.async.cg.shared.global [%0], [%1], 16;" :: "r"(dst), "l"(src));
}
__device__ __forceinline__ void cp_commit() {
    asm volatile("cp.async.commit_group;" ::: "memory");
}
__device__ __forceinline__ void wait_groups(int w) {
    if (w == 0)      asm volatile("cp.async.wait_group 0;" ::: "memory");
    else if (w == 1) asm volatile("cp.async.wait_group 1;" ::: "memory");
    else             asm volatile("cp.async.wait_group 2;" ::: "memory");
}
__device__ __forceinline__ void ldm_x4(uint32_t r[4], uint32_t addr) {
    asm volatile("ldmatrix.sync.aligned.m8n8.x4.shared.b16 {%0,%1,%2,%3}, [%4];"
        : "=r"(r[0]), "=r"(r[1]), "=r"(r[2]), "=r"(r[3]) : "r"(addr));
}
// fp16-accumulate HMMA: d = a*b + d, d is 2 regs (4 halves)
__device__ __forceinline__ void mma_f16acc(uint32_t d[2], const uint32_t a[4],
                                           uint32_t b0, uint32_t b1) {
    asm volatile(
        "mma.sync.aligned.m16n8k16.row.col.f16.f16.f16.f16 "
        "{%0,%1},{%2,%3,%4,%5},{%6,%7},{%0,%1};"
        : "+r"(d[0]), "+r"(d[1])
        : "r"(a[0]), "r"(a[1]), "r"(a[2]), "r"(a[3]), "r"(b0), "r"(b1));
}
__device__ __forceinline__ float fast_sigmoid(float v) {
    return __fdividef(1.f, 1.f + __expf(-v));
}
__device__ __forceinline__ float fast_tanh(float v) {
    return 1.f - __fdividef(2.f, __expf(2.f * v) + 1.f);
}

// ---- phase 1: fused converter (A rows then W rows) --------------------------
// W16 row j, j = b*24 + g*8 + w  (b = n8 block, g = gate, w = col in block)
__global__ void conv_kernel(const float* __restrict__ h, const float* __restrict__ x,
                            const float* __restrict__ glo,
                            const float* __restrict__ Wi, const float* __restrict__ Wf,
                            const float* __restrict__ Wc)
{
    const int bid = blockIdx.x;
    if (bid < BATCH) {
        const int m = bid;
        __half* dst = A16 + (size_t)m * KDIM;
        const float* h_r = h + (size_t)m * HDIM;
        const float* x_r = x + (size_t)m * 2 * HDIM;
        const float* g_r = glo + (size_t)m * HDIM;
#pragma unroll 1
        for (int f4 = threadIdx.x; f4 < KDIM / 4; f4 += 256) {
            int k = f4 * 4;
            const float* src = (k < HDIM) ? (h_r + k)
                             : (k < 3 * HDIM) ? (x_r + (k - HDIM))
                             : (g_r + (k - 3 * HDIM));
            float4 v = *(const float4*)src;
            __half2 p0 = __floats2half2_rn(v.x, v.y);
            __half2 p1 = __floats2half2_rn(v.z, v.w);
            uint2 u;
            u.x = *(const uint32_t*)&p0;
            u.y = *(const uint32_t*)&p1;
            *(uint2*)(dst + k) = u;
        }
    } else {
        const int j = bid - BATCH;
        const int b = j / 24, rem = j % 24;
        const int g = rem >> 3, w = rem & 7;
        const int n = b * 8 + w;
        const float* src_r = ((g == 0) ? Wi : (g == 1) ? Wf : Wc) + (size_t)n * KDIM;
        __half* dst = W16 + (size_t)j * KDIM;
#pragma unroll 1
        for (int f4 = threadIdx.x; f4 < KDIM / 4; f4 += 256) {
            int k = f4 * 4;
            float4 v = *(const float4*)(src_r + k);
            __half2 p0 = __floats2half2_rn(v.x, v.y);
            __half2 p1 = __floats2half2_rn(v.z, v.w);
            uint2 u;
            u.x = *(const uint32_t*)&p0;
            u.y = *(const uint32_t*)&p1;
            *(uint2*)(dst + k) = u;
        }
    }
}

// ---- phase 2: GEMM + fused epilogue ------------------------------------------
// Per stage: A 128 rows x 64B, B 192 rows x 64B, stride 80B; 1280 cp16.
__device__ __forceinline__ void issue_stage(uint32_t sbase, int tid, int kc, int m0, int rbase)
{
    const int k0 = kc * KC;
#pragma unroll
    for (int jj = 0; jj < 3; jj++) {
        int idx = tid + (jj << 9);
        if (idx < 512) {                        // A tile: 128 rows * 4
            int row = idx >> 2, c = idx & 3;
            const __half* src = A16 + (size_t)(m0 + row) * KDIM + k0 + c * 8;
            cp16(sbase + (uint32_t)row * ROW_BYTES + (uint32_t)c * 16u, src);
        } else if (idx < 1280) {                // B tile: 192 rows * 4
            int t = idx - 512;
            int row = t >> 2, c = t & 3;
            const __half* src = W16 + (size_t)(rbase + row) * KDIM + k0 + c * 8;
            cp16(sbase + A_TILE + (uint32_t)row * ROW_BYTES + (uint32_t)c * 16u, src);
        }
    }
    cp_commit();
}

__global__ void __launch_bounds__(512, 1) gazs_gemm_kernel(
    const float* __restrict__ h,
    const float* __restrict__ Wib, const float* __restrict__ Wfb,
    const float* __restrict__ Wcb, float* __restrict__ out)
{
    extern __shared__ __align__(128) char smem[];
    const uint32_t sb = smem_u32(smem);

    const int NC   = KDIM / KC;          // 128
    const int tid  = threadIdx.x;
    const int lane = tid & 31;
    const int wid  = tid >> 5;
    const int wn   = wid & 3;            // 4 n-groups, 48 B-rows each
    const int wm   = wid >> 2;           // 4 m-groups, 32 rows each
    const int m0   = blockIdx.y * BM;
    const int n0   = blockIdx.x * BN_GATE;
    const int rbase = blockIdx.x * BN;   // W16 row base
    const int qr   = lane >> 2;
    const int qc   = lane & 3;

    // ldmatrix per-lane base offsets
    const uint32_t a_lb = (uint32_t)((wm * 32 + (lane & 15)) * ROW_BYTES + (lane >> 4) * 16);
    const uint32_t b_lb = (uint32_t)((wn * 48 + (lane & 7) + ((lane & 16) ? 8 : 0)) * ROW_BYTES
                                     + ((lane >> 3) & 1) * 16);

    float acc[2][6][4];            // fp32 master accumulators
    uint32_t accH[2][6][2];        // fp16 short-span accumulators (4 halves each)
#pragma unroll
    for (int mt = 0; mt < 2; mt++)
#pragma unroll
        for (int nt = 0; nt < 6; nt++) {
#pragma unroll
            for (int c = 0; c < 4; c++) acc[mt][nt][c] = 0.f;
            accH[mt][nt][0] = 0u; accH[mt][nt][1] = 0u;
        }

    // prologue: 3 stages in flight
#pragma unroll
    for (int s = 0; s < NSTAGES - 1; s++)
        issue_stage(sb + (uint32_t)s * STAGE, tid, s, m0, rbase);

    for (int kc = 0; kc < NC; kc++) {
        int w = NC - 1 - kc; if (w > NSTAGES - 2) w = NSTAGES - 2;
        wait_groups(w);
        __syncthreads();

        int pf = kc + NSTAGES - 1;
        if (pf < NC)
            issue_stage(sb + (uint32_t)(pf & 3) * STAGE, tid, pf, m0, rbase);

        const uint32_t As = sb + (uint32_t)(kc & 3) * STAGE;
        const uint32_t Bs = As + A_TILE;

#pragma unroll
        for (int s = 0; s < 2; s++) {
            uint32_t a[2][4], b[3][4];
#pragma unroll
            for (int mt = 0; mt < 2; mt++)
                ldm_x4(a[mt], As + a_lb + (uint32_t)mt * (16 * ROW_BYTES) + (uint32_t)s * 32);
#pragma unroll
            for (int nb = 0; nb < 3; nb++)
                ldm_x4(b[nb], Bs + b_lb + (uint32_t)nb * (16 * ROW_BYTES) + (uint32_t)s * 32);
#pragma unroll
            for (int nb = 0; nb < 3; nb++)
#pragma unroll
                for (int mt = 0; mt < 2; mt++) {
                    mma_f16acc(accH[mt][2 * nb],     a[mt], b[nb][0], b[nb][1]);
                    mma_f16acc(accH[mt][2 * nb + 1], a[mt], b[nb][2], b[nb][3]);
                }
        }

        // spill f16 accumulators to fp32 every 4 chunks (128 k-elements)
        if ((kc & 3) == 3) {
#pragma unroll
            for (int mt = 0; mt < 2; mt++)
#pragma unroll
                for (int nt = 0; nt < 6; nt++) {
                    float2 v0 = __half22float2(*(__half2*)&accH[mt][nt][0]);
                    float2 v1 = __half22float2(*(__half2*)&accH[mt][nt][1]);
                    acc[mt][nt][0] += v0.x;
                    acc[mt][nt][1] += v0.y;
                    acc[mt][nt][2] += v1.x;
                    acc[mt][nt][3] += v1.y;
                    accH[mt][nt][0] = 0u;
                    accH[mt][nt][1] = 0u;
                }
        }
    }

    // ---- epilogue: in-register gate blend --------------------------------
    // acc[mt][bl*3+g]: rows m0+wm*32+mt*16+qr(+8); cols n0+(2*wn+bl)*8+qc*2(+1)
#pragma unroll
    for (int mt = 0; mt < 2; mt++) {
        const int rb = m0 + wm * 32 + mt * 16 + qr;
#pragma unroll
        for (int bl = 0; bl < 2; bl++) {
            const int n = n0 + (2 * wn + bl) * 8 + qc * 2;
            const float bi0 = __ldg(Wib + n), bi1 = __ldg(Wib + n + 1);
            const float bf0 = __ldg(Wfb + n), bf1 = __ldg(Wfb + n + 1);
            const float bc0 = __ldg(Wcb + n), bc1 = __ldg(Wcb + n + 1);
            const float* ai = acc[mt][bl * 3 + 0];
            const float* af = acc[mt][bl * 3 + 1];
            const float* ac = acc[mt][bl * 3 + 2];
#pragma unroll
            for (int rs = 0; rs < 2; rs++) {
                const int row = rb + rs * 8;
                const int i0 = rs * 2;
                float2 hv = *(const float2*)(h + (size_t)row * HDIM + n);

                float ig0 = fast_sigmoid(ai[i0] + bi0);
                float ig1 = fast_sigmoid(ai[i0 + 1] + bi1);
                float fg0 = fast_sigmoid(af[i0] + bf0);
                float fg1 = fast_sigmoid(af[i0 + 1] + bf1);
                float cg0 = fast_tanh(ac[i0] + bc0);
                float cg1 = fast_tanh(ac[i0 + 1] + bc1);
                float al0 = fast_sigmoid(ig0 - fg0);
                float al1 = fast_sigmoid(ig1 - fg1);

                float2 ov;
                ov.x = fmaf(al0, cg0 - hv.x, hv.x);
                ov.y = fmaf(al1, cg1 - hv.y, hv.y);
                *(float2*)(out + (size_t)row * HDIM + n) = ov;
            }
        }
    }
}

extern "C" void kernel_launch(void* const* d_in, const int* in_sizes, int n_in,
                              void* d_out, int out_size)
{
    const float* h   = (const float*)d_in[0];
    const float* x   = (const float*)d_in[1];
    const float* glo = (const float*)d_in[2];
    const float* Wi  = (const float*)d_in[3];
    const float* Wib = (const float*)d_in[4];
    const float* Wf  = (const float*)d_in[5];
    const float* Wfb = (const float*)d_in[6];
    const float* Wc  = (const float*)d_in[7];
    const float* Wcb = (const float*)d_in[8];
    float* out = (float*)d_out;

    cudaFuncSetAttribute(gazs_gemm_kernel,
                         cudaFuncAttributeMaxDynamicSharedMemorySize, DYN_SMEM);

    conv_kernel<<<BATCH + 3 * HDIM, 256>>>(h, x, glo, Wi, Wf, Wc);

    dim3 grid(HDIM / BN_GATE, BATCH / BM);   // (16, 64) = 1024 CTAs
    gazs_gemm_kernel<<<grid, 512, DYN_SMEM>>>(h, Wib, Wfb, Wcb, out);
}

// round 7
// speedup vs baseline: 1.0369x; 1.0369x over previous
#include <cuda_runtime.h>
#include <cuda_fp16.h>
#include <cstdint>

// ---------------------------------------------------------------------------
// Gazs cell, legacy tensor-core path, fp16 in / fp32 accum.
// R7: fix wave quantization. 2048 small CTAs (BM64 x BNG64, 256 thr,
// 8 warps = 2m x 4n, warp m32 x n48), 82KB smem -> 2 CTAs/SM resident.
// Mainloop identical instruction mix to R5 (known HMMA-issue-bound).
// ---------------------------------------------------------------------------

#define BM 64
#define BN_GATE 64
#define BN 192                     // 3 gates * 64 cols (B rows)
#define KC 32                      // fp16 k per stage (64B rows)
#define NSTAGES 4
#define ROW_BYTES 80               // 64B data + 16B pad
#define A_TILE (BM * ROW_BYTES)            // 5120
#define B_TILE (BN * ROW_BYTES)            // 15360
#define STAGE  (A_TILE + B_TILE)           // 20480
#define DYN_SMEM (NSTAGES * STAGE)         // 81920  -> 2 CTAs/SM

#define BATCH 8192
#define HDIM  1024
#define KDIM  4096

__device__ __align__(16) __half A16[(size_t)BATCH * KDIM];
__device__ __align__(16) __half W16[(size_t)3 * HDIM * KDIM];

// ---- helpers ---------------------------------------------------------------
__device__ __forceinline__ uint32_t smem_u32(const void* p) {
    uint32_t a;
    asm("{ .reg .u64 t; cvta.to.shared.u64 t, %1; cvt.u32.u64 %0, t; }" : "=r"(a) : "l"(p));
    return a;
}
__device__ __forceinline__ void cp16(uint32_t dst, const void* src) {
    asm volatile("cp.async.cg.shared.global [%0], [%1], 16;" :: "r"(dst), "l"(src));
}
__device__ __forceinline__ void cp_commit() {
    asm volatile("cp.async.commit_group;" ::: "memory");
}
__device__ __forceinline__ void wait_groups(int w) {
    if (w == 0)      asm volatile("cp.async.wait_group 0;" ::: "memory");
    else if (w == 1) asm volatile("cp.async.wait_group 1;" ::: "memory");
    else             asm volatile("cp.async.wait_group 2;" ::: "memory");
}
__device__ __forceinline__ void ldm_x4(uint32_t r[4], uint32_t addr) {
    asm volatile("ldmatrix.sync.aligned.m8n8.x4.shared.b16 {%0,%1,%2,%3}, [%4];"
        : "=r"(r[0]), "=r"(r[1]), "=r"(r[2]), "=r"(r[3]) : "r"(addr));
}
__device__ __forceinline__ void mma_f16(float d[4], const uint32_t a[4],
                                        uint32_t b0, uint32_t b1) {
    asm volatile(
        "mma.sync.aligned.m16n8k16.row.col.f32.f16.f16.f32 "
        "{%0,%1,%2,%3},{%4,%5,%6,%7},{%8,%9},{%0,%1,%2,%3};"
        : "+f"(d[0]), "+f"(d[1]), "+f"(d[2]), "+f"(d[3])
        : "r"(a[0]), "r"(a[1]), "r"(a[2]), "r"(a[3]), "r"(b0), "r"(b1));
}
__device__ __forceinline__ float fast_sigmoid(float v) {
    return __fdividef(1.f, 1.f + __expf(-v));
}
__device__ __forceinline__ float fast_tanh(float v) {
    return 1.f - __fdividef(2.f, __expf(2.f * v) + 1.f);
}

// ---- phase 1: fused converter (A rows then W rows) --------------------------
// W16 row j, j = b*24 + g*8 + w  (b = n8 block, g = gate, w = col in block)
__global__ void conv_kernel(const float* __restrict__ h, const float* __restrict__ x,
                            const float* __restrict__ glo,
                            const float* __restrict__ Wi, const float* __restrict__ Wf,
                            const float* __restrict__ Wc)
{
    const int bid = blockIdx.x;
    if (bid < BATCH) {
        const int m = bid;
        __half* dst = A16 + (size_t)m * KDIM;
        const float* h_r = h + (size_t)m * HDIM;
        const float* x_r = x + (size_t)m * 2 * HDIM;
        const float* g_r = glo + (size_t)m * HDIM;
#pragma unroll 1
        for (int f4 = threadIdx.x; f4 < KDIM / 4; f4 += 256) {
            int k = f4 * 4;
            const float* src = (k < HDIM) ? (h_r + k)
                             : (k < 3 * HDIM) ? (x_r + (k - HDIM))
                             : (g_r + (k - 3 * HDIM));
            float4 v = *(const float4*)src;
            __half2 p0 = __floats2half2_rn(v.x, v.y);
            __half2 p1 = __floats2half2_rn(v.z, v.w);
            uint2 u;
            u.x = *(const uint32_t*)&p0;
            u.y = *(const uint32_t*)&p1;
            *(uint2*)(dst + k) = u;
        }
    } else {
        const int j = bid - BATCH;
        const int b = j / 24, rem = j % 24;
        const int g = rem >> 3, w = rem & 7;
        const int n = b * 8 + w;
        const float* src_r = ((g == 0) ? Wi : (g == 1) ? Wf : Wc) + (size_t)n * KDIM;
        __half* dst = W16 + (size_t)j * KDIM;
#pragma unroll 1
        for (int f4 = threadIdx.x; f4 < KDIM / 4; f4 += 256) {
            int k = f4 * 4;
            float4 v = *(const float4*)(src_r + k);
            __half2 p0 = __floats2half2_rn(v.x, v.y);
            __half2 p1 = __floats2half2_rn(v.z, v.w);
            uint2 u;
            u.x = *(const uint32_t*)&p0;
            u.y = *(const uint32_t*)&p1;
            *(uint2*)(dst + k) = u;
        }
    }
}

// ---- phase 2: GEMM + fused epilogue ------------------------------------------
// Per stage: A 64 rows x 64B + B 192 rows x 64B, stride 80B; 1024 cp16.
__device__ __forceinline__ void issue_stage(uint32_t sbase, int tid, int kc, int m0, int rbase)
{
    const int k0 = kc * KC;
#pragma unroll
    for (int jj = 0; jj < 4; jj++) {
        int idx = tid + (jj << 8);
        if (idx < 256) {                        // A tile: 64 rows * 4
            int row = idx >> 2, c = idx & 3;
            const __half* src = A16 + (size_t)(m0 + row) * KDIM + k0 + c * 8;
            cp16(sbase + (uint32_t)row * ROW_BYTES + (uint32_t)c * 16u, src);
        } else {                                // B tile: 192 rows * 4
            int t = idx - 256;
            int row = t >> 2, c = t & 3;
            const __half* src = W16 + (size_t)(rbase + row) * KDIM + k0 + c * 8;
            cp16(sbase + A_TILE + (uint32_t)row * ROW_BYTES + (uint32_t)c * 16u, src);
        }
    }
    cp_commit();
}

__global__ void __launch_bounds__(256, 2) gazs_gemm_kernel(
    const float* __restrict__ h,
    const float* __restrict__ Wib, const float* __restrict__ Wfb,
    const float* __restrict__ Wcb, float* __restrict__ out)
{
    extern __shared__ __align__(128) char smem[];
    const uint32_t sb = smem_u32(smem);

    const int NC   = KDIM / KC;          // 128
    const int tid  = threadIdx.x;
    const int lane = tid & 31;
    const int wid  = tid >> 5;
    const int wn   = wid & 3;            // 4 n-groups, 48 B-rows each
    const int wm   = wid >> 2;           // 2 m-groups, 32 rows each
    const int m0   = blockIdx.y * BM;
    const int n0   = blockIdx.x * BN_GATE;
    const int rbase = blockIdx.x * BN;   // W16 row base
    const int qr   = lane >> 2;
    const int qc   = lane & 3;

    // ldmatrix per-lane base offsets
    const uint32_t a_lb = (uint32_t)((wm * 32 + (lane & 15)) * ROW_BYTES + (lane >> 4) * 16);
    const uint32_t b_lb = (uint32_t)((wn * 48 + (lane & 7) + ((lane & 16) ? 8 : 0)) * ROW_BYTES
                                     + ((lane >> 3) & 1) * 16);

    float acc[2][6][4];
#pragma unroll
    for (int mt = 0; mt < 2; mt++)
#pragma unroll
        for (int nt = 0; nt < 6; nt++)
#pragma unroll
            for (int c = 0; c < 4; c++) acc[mt][nt][c] = 0.f;

    // prologue: 3 stages in flight
#pragma unroll
    for (int s = 0; s < NSTAGES - 1; s++)
        issue_stage(sb + (uint32_t)s * STAGE, tid, s, m0, rbase);

    for (int kc = 0; kc < NC; kc++) {
        int w = NC - 1 - kc; if (w > NSTAGES - 2) w = NSTAGES - 2;
        wait_groups(w);
        __syncthreads();

        int pf = kc + NSTAGES - 1;
        if (pf < NC)
            issue_stage(sb + (uint32_t)(pf & 3) * STAGE, tid, pf, m0, rbase);

        const uint32_t As = sb + (uint32_t)(kc & 3) * STAGE;
        const uint32_t Bs = As + A_TILE;

#pragma unroll
        for (int s = 0; s < 2; s++) {
            uint32_t a[2][4], b[3][4];
#pragma unroll
            for (int mt = 0; mt < 2; mt++)
                ldm_x4(a[mt], As + a_lb + (uint32_t)mt * (16 * ROW_BYTES) + (uint32_t)s * 32);
#pragma unroll
            for (int nb = 0; nb < 3; nb++)
                ldm_x4(b[nb], Bs + b_lb + (uint32_t)nb * (16 * ROW_BYTES) + (uint32_t)s * 32);
#pragma unroll
            for (int nb = 0; nb < 3; nb++)
#pragma unroll
                for (int mt = 0; mt < 2; mt++) {
                    mma_f16(acc[mt][2 * nb],     a[mt], b[nb][0], b[nb][1]);
                    mma_f16(acc[mt][2 * nb + 1], a[mt], b[nb][2], b[nb][3]);
                }
        }
    }

    // ---- epilogue: in-register gate blend --------------------------------
    // acc[mt][bl*3+g]: rows m0+wm*32+mt*16+qr(+8); cols n0+(2*wn+bl)*8+qc*2(+1)
#pragma unroll
    for (int mt = 0; mt < 2; mt++) {
        const int rb = m0 + wm * 32 + mt * 16 + qr;
#pragma unroll
        for (int bl = 0; bl < 2; bl++) {
            const int n = n0 + (2 * wn + bl) * 8 + qc * 2;
            const float bi0 = __ldg(Wib + n), bi1 = __ldg(Wib + n + 1);
            const float bf0 = __ldg(Wfb + n), bf1 = __ldg(Wfb + n + 1);
            const float bc0 = __ldg(Wcb + n), bc1 = __ldg(Wcb + n + 1);
            const float* ai = acc[mt][bl * 3 + 0];
            const float* af = acc[mt][bl * 3 + 1];
            const float* ac = acc[mt][bl * 3 + 2];
#pragma unroll
            for (int rs = 0; rs < 2; rs++) {
                const int row = rb + rs * 8;
                const int i0 = rs * 2;
                float2 hv = *(const float2*)(h + (size_t)row * HDIM + n);

                float ig0 = fast_sigmoid(ai[i0] + bi0);
                float ig1 = fast_sigmoid(ai[i0 + 1] + bi1);
                float fg0 = fast_sigmoid(af[i0] + bf0);
                float fg1 = fast_sigmoid(af[i0 + 1] + bf1);
                float cg0 = fast_tanh(ac[i0] + bc0);
                float cg1 = fast_tanh(ac[i0 + 1] + bc1);
                float al0 = fast_sigmoid(ig0 - fg0);
                float al1 = fast_sigmoid(ig1 - fg1);

                float2 ov;
                ov.x = fmaf(al0, cg0 - hv.x, hv.x);
                ov.y = fmaf(al1, cg1 - hv.y, hv.y);
                *(float2*)(out + (size_t)row * HDIM + n) = ov;
            }
        }
    }
}

extern "C" void kernel_launch(void* const* d_in, const int* in_sizes, int n_in,
                              void* d_out, int out_size)
{
    const float* h   = (const float*)d_in[0];
    const float* x   = (const float*)d_in[1];
    const float* glo = (const float*)d_in[2];
    const float* Wi  = (const float*)d_in[3];
    const float* Wib = (const float*)d_in[4];
    const float* Wf  = (const float*)d_in[5];
    const float* Wfb = (const float*)d_in[6];
    const float* Wc  = (const float*)d_in[7];
    const float* Wcb = (const float*)d_in[8];
    float* out = (float*)d_out;

    cudaFuncSetAttribute(gazs_gemm_kernel,
                         cudaFuncAttributeMaxDynamicSharedMemorySize, DYN_SMEM);

    conv_kernel<<<BATCH + 3 * HDIM, 256>>>(h, x, glo, Wi, Wf, Wc);

    dim3 grid(HDIM / BN_GATE, BATCH / BM);   // (16, 128) = 2048 CTAs
    gazs_gemm_kernel<<<grid, 256, DYN_SMEM>>>(h, Wib, Wfb, Wcb, out);
}

// round 8
// speedup vs baseline: 1.0621x; 1.0242x over previous
#include <cuda_runtime.h>
#include <cuda_fp16.h>
#include <cstdint>

// ---------------------------------------------------------------------------
// Gazs cell, legacy tensor-core path, fp16 in / fp32 accum.
// R8: R5 mainloop (measured at the mma.sync issue floor, ~16.2 cyc/SMSP)
// + h-tile smem prefetch hidden in stage-0 cp.async group
// + conv kernel with 4 rows/block for better HBM ramp.
// ---------------------------------------------------------------------------

#define BM 128
#define BN_GATE 128
#define BN 384                     // 3 gates * 128 cols (B rows)
#define KC 32                      // fp16 k per stage (64B rows)
#define NSTAGES 4
#define ROW_BYTES 80               // 64B data + 16B pad
#define A_TILE (BM * ROW_BYTES)            // 10240
#define B_TILE (BN * ROW_BYTES)            // 30720
#define STAGE  (A_TILE + B_TILE)           // 40960
#define OFF_H  (NSTAGES * STAGE)           // 163840
#define H_STRIDE_F 132                     // floats per h row (128 + 4 pad)
#define H_STRIDE_B (H_STRIDE_F * 4)        // 528 bytes
#define DYN_SMEM (OFF_H + BM * H_STRIDE_B) // 231424 (<= 232448 opt-in max)

#define BATCH 8192
#define HDIM  1024
#define KDIM  4096

__device__ __align__(16) __half A16[(size_t)BATCH * KDIM];
__device__ __align__(16) __half W16[(size_t)3 * HDIM * KDIM];

// ---- helpers ---------------------------------------------------------------
__device__ __forceinline__ uint32_t smem_u32(const void* p) {
    uint32_t a;
    asm("{ .reg .u64 t; cvta.to.shared.u64 t, %1; cvt.u32.u64 %0, t; }" : "=r"(a) : "l"(p));
    return a;
}
__device__ __forceinline__ void cp16(uint32_t dst, const void* src) {
    asm volatile("cp.async.cg.shared.global [%0], [%1], 16;" :: "r"(dst), "l"(src));
}
__device__ __forceinline__ void cp_commit() {
    asm volatile("cp.async.commit_group;" ::: "memory");
}
__device__ __forceinline__ void wait_groups(int w) {
    if (w == 0)      asm volatile("cp.async.wait_group 0;" ::: "memory");
    else if (w == 1) asm volatile("cp.async.wait_group 1;" ::: "memory");
    else             asm volatile("cp.async.wait_group 2;" ::: "memory");
}
__device__ __forceinline__ void ldm_x4(uint32_t r[4], uint32_t addr) {
    asm volatile("ldmatrix.sync.aligned.m8n8.x4.shared.b16 {%0,%1,%2,%3}, [%4];"
        : "=r"(r[0]), "=r"(r[1]), "=r"(r[2]), "=r"(r[3]) : "r"(addr));
}
__device__ __forceinline__ void mma_f16(float d[4], const uint32_t a[4],
                                        uint32_t b0, uint32_t b1) {
    asm volatile(
        "mma.sync.aligned.m16n8k16.row.col.f32.f16.f16.f32 "
        "{%0,%1,%2,%3},{%4,%5,%6,%7},{%8,%9},{%0,%1,%2,%3};"
        : "+f"(d[0]), "+f"(d[1]), "+f"(d[2]), "+f"(d[3])
        : "r"(a[0]), "r"(a[1]), "r"(a[2]), "r"(a[3]), "r"(b0), "r"(b1));
}
__device__ __forceinline__ float fast_sigmoid(float v) {
    return __fdividef(1.f, 1.f + __expf(-v));
}
__device__ __forceinline__ float fast_tanh(float v) {
    return 1.f - __fdividef(2.f, __expf(2.f * v) + 1.f);
}

// ---- phase 1: fused converter, 4 rows per block ------------------------------
// A rows: blocks [0, 2048); W rows: blocks [2048, 2816), gate-interleaved
// W16 row j, j = b*24 + g*8 + w  (b = n8 block, g = gate, w = col in block)
__global__ void conv_kernel(const float* __restrict__ h, const float* __restrict__ x,
                            const float* __restrict__ glo,
                            const float* __restrict__ Wi, const float* __restrict__ Wf,
                            const float* __restrict__ Wc)
{
    const int bid = blockIdx.x;
    if (bid < BATCH / 4) {
#pragma unroll 1
        for (int r = 0; r < 4; r++) {
            const int m = bid * 4 + r;
            __half* dst = A16 + (size_t)m * KDIM;
            const float* h_r = h + (size_t)m * HDIM;
            const float* x_r = x + (size_t)m * 2 * HDIM;
            const float* g_r = glo + (size_t)m * HDIM;
#pragma unroll 1
            for (int f4 = threadIdx.x; f4 < KDIM / 4; f4 += 256) {
                int k = f4 * 4;
                const float* src = (k < HDIM) ? (h_r + k)
                                 : (k < 3 * HDIM) ? (x_r + (k - HDIM))
                                 : (g_r + (k - 3 * HDIM));
                float4 v = *(const float4*)src;
                __half2 p0 = __floats2half2_rn(v.x, v.y);
                __half2 p1 = __floats2half2_rn(v.z, v.w);
                uint2 u;
                u.x = *(const uint32_t*)&p0;
                u.y = *(const uint32_t*)&p1;
                *(uint2*)(dst + k) = u;
            }
        }
    } else {
#pragma unroll 1
        for (int r = 0; r < 4; r++) {
            const int j = (bid - BATCH / 4) * 4 + r;
            const int b = j / 24, rem = j % 24;
            const int g = rem >> 3, w = rem & 7;
            const int n = b * 8 + w;
            const float* src_r = ((g == 0) ? Wi : (g == 1) ? Wf : Wc) + (size_t)n * KDIM;
            __half* dst = W16 + (size_t)j * KDIM;
#pragma unroll 1
            for (int f4 = threadIdx.x; f4 < KDIM / 4; f4 += 256) {
                int k = f4 * 4;
                float4 v = *(const float4*)(src_r + k);
                __half2 p0 = __floats2half2_rn(v.x, v.y);
                __half2 p1 = __floats2half2_rn(v.z, v.w);
                uint2 u;
                u.x = *(const uint32_t*)&p0;
                u.y = *(const uint32_t*)&p1;
                *(uint2*)(dst + k) = u;
            }
        }
    }
}

// ---- phase 2: GEMM + fused epilogue ------------------------------------------
// Per stage: A 128 rows x 64B + B 384 rows x 64B, stride 80B; 2048 cp16.
__device__ __forceinline__ void issue_stage(uint32_t sbase, int tid, int kc, int m0, int rbase)
{
    const int k0 = kc * KC;
#pragma unroll
    for (int jj = 0; jj < 4; jj++) {
        int idx = tid + (jj << 9);
        if (idx < 512) {                        // A tile: 128 rows * 4
            int row = idx >> 2, c = idx & 3;
            const __half* src = A16 + (size_t)(m0 + row) * KDIM + k0 + c * 8;
            cp16(sbase + (uint32_t)row * ROW_BYTES + (uint32_t)c * 16u, src);
        } else {                                // B tile: 384 rows * 4
            int t = idx - 512;
            int row = t >> 2, c = t & 3;
            const __half* src = W16 + (size_t)(rbase + row) * KDIM + k0 + c * 8;
            cp16(sbase + A_TILE + (uint32_t)row * ROW_BYTES + (uint32_t)c * 16u, src);
        }
    }
    cp_commit();
}

__global__ void __launch_bounds__(512, 1) gazs_gemm_kernel(
    const float* __restrict__ h,
    const float* __restrict__ Wib, const float* __restrict__ Wfb,
    const float* __restrict__ Wcb, float* __restrict__ out)
{
    extern __shared__ __align__(128) char smem[];
    const uint32_t sb = smem_u32(smem);

    const int NC   = KDIM / KC;          // 128
    const int tid  = threadIdx.x;
    const int lane = tid & 31;
    const int wid  = tid >> 5;
    const int wn   = wid & 3;            // 4 n-groups, 96 B-rows each
    const int wm   = wid >> 2;           // 4 m-groups, 32 rows each
    const int m0   = blockIdx.y * BM;
    const int n0   = blockIdx.x * BN_GATE;
    const int rbase = blockIdx.x * BN;   // W16 row base
    const int qr   = lane >> 2;
    const int qc   = lane & 3;

    // ldmatrix per-lane base offsets
    const uint32_t a_lb = (uint32_t)((wm * 32 + (lane & 15)) * ROW_BYTES + (lane >> 4) * 16);
    const uint32_t b_lb = (uint32_t)((wn * 96 + (lane & 7) + ((lane & 16) ? 8 : 0)) * ROW_BYTES
                                     + ((lane >> 3) & 1) * 16);

    float acc[2][12][4];
#pragma unroll
    for (int mt = 0; mt < 2; mt++)
#pragma unroll
        for (int nt = 0; nt < 12; nt++)
#pragma unroll
            for (int c = 0; c < 4; c++) acc[mt][nt][c] = 0.f;

    // ---- prologue: h-tile prefetch joins stage-0's cp.async group ---------
    // 128 rows x 128 fp32 = 4096 x 16B, padded rows of 132 floats in smem.
#pragma unroll
    for (int j = 0; j < 8; j++) {
        int idx = tid + (j << 9);
        int row = idx >> 5, c = idx & 31;
        cp16(sb + OFF_H + (uint32_t)row * H_STRIDE_B + (uint32_t)c * 16u,
             h + (size_t)(m0 + row) * HDIM + n0 + c * 4);
    }
#pragma unroll
    for (int s = 0; s < NSTAGES - 1; s++)
        issue_stage(sb + (uint32_t)s * STAGE, tid, s, m0, rbase);

    for (int kc = 0; kc < NC; kc++) {
        int w = NC - 1 - kc; if (w > NSTAGES - 2) w = NSTAGES - 2;
        wait_groups(w);
        __syncthreads();

        int pf = kc + NSTAGES - 1;
        if (pf < NC)
            issue_stage(sb + (uint32_t)(pf & 3) * STAGE, tid, pf, m0, rbase);

        const uint32_t As = sb + (uint32_t)(kc & 3) * STAGE;
        const uint32_t Bs = As + A_TILE;

#pragma unroll
        for (int s = 0; s < 2; s++) {
            uint32_t a0[4], a1[4];
            ldm_x4(a0, As + a_lb + (uint32_t)s * 32);
            ldm_x4(a1, As + a_lb + (uint32_t)(16 * ROW_BYTES) + (uint32_t)s * 32);

            uint32_t bcur[4], bnxt[4];
            ldm_x4(bcur, Bs + b_lb + (uint32_t)s * 32);
#pragma unroll
            for (int nb = 0; nb < 6; nb++) {
                if (nb < 5)
                    ldm_x4(bnxt, Bs + b_lb + (uint32_t)((nb + 1) * 16 * ROW_BYTES)
                                 + (uint32_t)s * 32);
                mma_f16(acc[0][2 * nb],     a0, bcur[0], bcur[1]);
                mma_f16(acc[0][2 * nb + 1], a0, bcur[2], bcur[3]);
                mma_f16(acc[1][2 * nb],     a1, bcur[0], bcur[1]);
                mma_f16(acc[1][2 * nb + 1], a1, bcur[2], bcur[3]);
#pragma unroll
                for (int q = 0; q < 4; q++) bcur[q] = bnxt[q];
            }
        }
    }

    // ---- epilogue: in-register gate blend, h from smem --------------------
    const float* hs = (const float*)(smem + OFF_H);
#pragma unroll
    for (int mt = 0; mt < 2; mt++) {
        const int rl = wm * 32 + mt * 16 + qr;       // row within tile
#pragma unroll
        for (int bl = 0; bl < 4; bl++) {
            const int nl = (wn * 4 + bl) * 8 + qc * 2;   // col within tile
            const int n = n0 + nl;
            const float bi0 = __ldg(Wib + n), bi1 = __ldg(Wib + n + 1);
            const float bf0 = __ldg(Wfb + n), bf1 = __ldg(Wfb + n + 1);
            const float bc0 = __ldg(Wcb + n), bc1 = __ldg(Wcb + n + 1);
            const float* ai = acc[mt][bl * 3 + 0];
            const float* af = acc[mt][bl * 3 + 1];
            const float* ac = acc[mt][bl * 3 + 2];
#pragma unroll
            for (int rs = 0; rs < 2; rs++) {
                const int row = rl + rs * 8;
                const int i0 = rs * 2;
                float hv0 = hs[row * H_STRIDE_F + nl];
                float hv1 = hs[row * H_STRIDE_F + nl + 1];

                float ig0 = fast_sigmoid(ai[i0] + bi0);
                float ig1 = fast_sigmoid(ai[i0 + 1] + bi1);
                float fg0 = fast_sigmoid(af[i0] + bf0);
                float fg1 = fast_sigmoid(af[i0 + 1] + bf1);
                float cg0 = fast_tanh(ac[i0] + bc0);
                float cg1 = fast_tanh(ac[i0 + 1] + bc1);
                float al0 = fast_sigmoid(ig0 - fg0);
                float al1 = fast_sigmoid(ig1 - fg1);

                float2 ov;
                ov.x = fmaf(al0, cg0 - hv0, hv0);
                ov.y = fmaf(al1, cg1 - hv1, hv1);
                *(float2*)(out + (size_t)(m0 + row) * HDIM + n) = ov;
            }
        }
    }
}

extern "C" void kernel_launch(void* const* d_in, const int* in_sizes, int n_in,
                              void* d_out, int out_size)
{
    const float* h   = (const float*)d_in[0];
    const float* x   = (const float*)d_in[1];
    const float* glo = (const float*)d_in[2];
    const float* Wi  = (const float*)d_in[3];
    const float* Wib = (const float*)d_in[4];
    const float* Wf  = (const float*)d_in[5];
    const float* Wfb = (const float*)d_in[6];
    const float* Wc  = (const float*)d_in[7];
    const float* Wcb = (const float*)d_in[8];
    float* out = (float*)d_out;

    cudaFuncSetAttribute(gazs_gemm_kernel,
                         cudaFuncAttributeMaxDynamicSharedMemorySize, DYN_SMEM);

    conv_kernel<<<(BATCH + 3 * HDIM) / 4, 256>>>(h, x, glo, Wi, Wf, Wc);

    dim3 grid(HDIM / BN_GATE, BATCH / BM);   // (8, 64) = 512 CTAs
    gazs_gemm_kernel<<<grid, 512, DYN_SMEM>>>(h, Wib, Wfb, Wcb, out);
}